// round 11
// baseline (speedup 1.0000x reference)
#include <cuda_runtime.h>
#include <cstdint>

// Problem dims
#define B_  64
#define S_  512
#define I_  512
#define H_  1024
#define G_  4096          // 4*H
#define BH_ (B_*H_)       // 65536
#define OUT_ELEMS (B_*S_*H_)   // 33554432

#define NCTA  128
#define NTHR  544         // 512 consumers + 32 producer warp
#define NCONS 512
#define NCH   16          // K-chunks of 64 per 1024-wide matrix (storage layout)

// persistent-kernel smem plan
// 3 stages x 64KB: [0,32768) B(h), [32768,49152) A0, [49152,65536) A1
// partial-sum buffer overlays stage area after consumption: 8 x 17408B
#define STG_SZ 65536
#define NSTG   3
#define SM_BI  196608
#define SM_MB  196736     // full[3] @ +0, empty[3] @ +24
#define SM_TOT 196800

// ---------------- device scratch (static, allowed) ----------------
__device__ float  g_Wx0p[G_*I_];            // tf32-rounded, gate-permuted rows (for precompute)
__device__ float  g_b0p[G_];                // bx0+bh0, permuted (folded into G0)
__device__ float  g_b1p[G_];                // bx1+bh1, permuted
__device__ float4 g_A0[(size_t)NCTA*NCH*512];  // Wh0 fragment-major
__device__ float4 g_A1[(size_t)NCTA*NCH*512];  // Wx1
__device__ float4 g_A2[(size_t)NCTA*NCH*512];  // Wh1
__device__ float  g_G0[(size_t)S_*B_*G_];   // x-path preactivations [t][b][prow] (512MB)
__device__ float4 g_h0F[2][16384];          // h0 fragment-major, double buffered
__device__ float4 g_h1F[2][16384];          // h1 fragment-major
// fine-grained progress: group g = CTAs [16g,16g+16) own h units [128g,128g+128)
__device__ volatile unsigned g_cnt0[8];     // h0 progress (monotonic epochs)
__device__ volatile unsigned g_cnt1[8];     // h1 progress

// ---------------- helpers ----------------
__device__ __forceinline__ float f2tf_f(float f) {
    uint32_t r;
    asm("cvt.rna.tf32.f32 %0, %1;" : "=r"(r) : "f"(f));
    return __uint_as_float(r);
}

__device__ __forceinline__ void mma_tf32(float* d, float4 a, float2 b) {
    asm volatile(
        "mma.sync.aligned.m16n8k8.row.col.f32.tf32.tf32.f32 "
        "{%0,%1,%2,%3}, {%4,%5,%6,%7}, {%8,%9}, {%0,%1,%2,%3};\n"
        : "+f"(d[0]), "+f"(d[1]), "+f"(d[2]), "+f"(d[3])
        : "r"(__float_as_uint(a.x)), "r"(__float_as_uint(a.y)),
          "r"(__float_as_uint(a.z)), "r"(__float_as_uint(a.w)),
          "r"(__float_as_uint(b.x)), "r"(__float_as_uint(b.y)));
}

__device__ __forceinline__ float sigmoidf_(float x) { return 1.0f / (1.0f + expf(-x)); }

// ---- TMA bulk + mbarrier machinery ----
__device__ __forceinline__ void mbar_init(uint32_t addr, uint32_t count) {
    asm volatile("mbarrier.init.shared.b64 [%0], %1;" :: "r"(addr), "r"(count) : "memory");
}
__device__ __forceinline__ void mbar_expect_tx(uint32_t addr, uint32_t bytes) {
    asm volatile("mbarrier.arrive.expect_tx.shared.b64 _, [%0], %1;"
                 :: "r"(addr), "r"(bytes) : "memory");
}
__device__ __forceinline__ void mbar_arrive(uint32_t addr) {
    asm volatile("mbarrier.arrive.shared.b64 _, [%0];" :: "r"(addr) : "memory");
}
__device__ __forceinline__ void bulk_g2s(uint32_t dst, const void* src,
                                         uint32_t bytes, uint32_t mbar) {
    asm volatile(
        "cp.async.bulk.shared::cta.global.mbarrier::complete_tx::bytes [%0], [%1], %2, [%3];"
        :: "r"(dst), "l"(src), "r"(bytes), "r"(mbar) : "memory");
}
__device__ __forceinline__ void mbar_wait(uint32_t mbar, uint32_t parity) {
    asm volatile(
        "{\n\t"
        ".reg .pred P;\n\t"
        "WAIT_LOOP_%=:\n\t"
        "mbarrier.try_wait.parity.acquire.cta.shared::cta.b64 P, [%0], %1, 0x989680;\n\t"
        "@P bra.uni WAIT_DONE_%=;\n\t"
        "bra.uni WAIT_LOOP_%=;\n\t"
        "WAIT_DONE_%=:\n\t"
        "}"
        :: "r"(mbar), "r"(parity) : "memory");
}

// Row permutation: prow = (u/8)*32 + q*8 + (u%8); CTA c owns units [8c,8c+8).

// ---------------- fused prep: counters + Wx0/bias convert + fragment convert ----------------
__global__ void __launch_bounds__(256) convert_all(
    const float* __restrict__ Wx0, const float* __restrict__ Wh0,
    const float* __restrict__ Wx1, const float* __restrict__ Wh1,
    const float* __restrict__ bx0, const float* __restrict__ bh0,
    const float* __restrict__ bx1, const float* __restrict__ bh1)
{
    const int gtid = blockIdx.x * blockDim.x + threadIdx.x;
    if (gtid < 8) { g_cnt0[gtid] = 0; g_cnt1[gtid] = 0; }

    // part 1: Wx0 (prow-major, tf32) + biases
    {
        const int total = G_ * I_;
        for (int i = gtid; i < total; i += gridDim.x * blockDim.x) {
            int prow = i / I_;
            int k    = i - prow * I_;
            int u    = ((prow >> 5) << 3) + (prow & 7);
            int q    = (prow >> 3) & 3;
            int orig = q * H_ + u;
            g_Wx0p[i] = f2tf_f(Wx0[(size_t)orig * I_ + k]);
            if (k == 0) {
                g_b0p[prow] = bx0[orig] + bh0[orig];
                g_b1p[prow] = bx1[orig] + bh1[orig];
            }
        }
    }
    // part 2: fragment-major recurrent weights
    {
        const int total = NCTA * NCH * 512;
        for (int idx = gtid; idx < total; idx += gridDim.x * blockDim.x) {
            int lane = idx & 31;
            int kk   = (idx >> 5) & 7;
            int wm   = (idx >> 8) & 1;
            int ch   = (idx >> 9) & 15;
            int c    = idx >> 13;
            int g4 = lane >> 2, t4 = lane & 3;
            int p0 = wm * 16 + g4;
            int q0 = p0 >> 3, v = p0 & 7;
            int o0 = q0 * H_ + c * 8 + v;
            int k  = ch * 64 + kk * 8 + t4;
            size_t r0 = (size_t)o0 * H_ + k;
            size_t r1 = r0 + (size_t)H_ * H_;
            g_A0[idx] = make_float4(f2tf_f(Wh0[r0]), f2tf_f(Wh0[r1]),
                                    f2tf_f(Wh0[r0 + 4]), f2tf_f(Wh0[r1 + 4]));
            g_A1[idx] = make_float4(f2tf_f(Wx1[r0]), f2tf_f(Wx1[r1]),
                                    f2tf_f(Wx1[r0 + 4]), f2tf_f(Wx1[r1 + 4]));
            g_A2[idx] = make_float4(f2tf_f(Wh1[r0]), f2tf_f(Wh1[r1]),
                                    f2tf_f(Wh1[r0 + 4]), f2tf_f(Wh1[r1 + 4]));
        }
    }
}

// ---------------- x-path precompute: G0 = x@Wx0p^T + b0p ----------------
__global__ void __launch_bounds__(256, 1) precompute_kernel(const float* __restrict__ x)
{
    __shared__ float As[128][20];
    __shared__ float Bs[128][20];

    const int tid  = threadIdx.x;
    const int w    = tid >> 5;
    const int lane = tid & 31;
    const int wM   = w >> 2;
    const int wN   = w & 3;
    const int mBase = blockIdx.y * 128;
    const int nBase = blockIdx.x * 128;
    const int g4 = lane >> 2;
    const int t4 = lane & 3;

    float acc[4][4][4];
#pragma unroll
    for (int mt = 0; mt < 4; mt++)
#pragma unroll
        for (int nt = 0; nt < 4; nt++)
#pragma unroll
            for (int e = 0; e < 4; e++) acc[mt][nt][e] = 0.0f;

    for (int kc = 0; kc < I_; kc += 16) {
#pragma unroll
        for (int it = 0; it < 2; it++) {
            int i  = tid + it * 256;
            int r  = i >> 2;
            int c4 = (i & 3) * 4;
            int m  = mBase + r;
            int tt = m >> 6;
            int bb = m & 63;
            float4 v = *(const float4*)(x + ((size_t)bb * S_ + tt) * I_ + kc + c4);
            As[r][c4 + 0] = f2tf_f(v.x); As[r][c4 + 1] = f2tf_f(v.y);
            As[r][c4 + 2] = f2tf_f(v.z); As[r][c4 + 3] = f2tf_f(v.w);
        }
#pragma unroll
        for (int it = 0; it < 2; it++) {
            int i  = tid + it * 256;
            int r  = i >> 2;
            int c4 = (i & 3) * 4;
            float4 v = *(const float4*)(g_Wx0p + (size_t)(nBase + r) * I_ + kc + c4);
            Bs[r][c4 + 0] = v.x; Bs[r][c4 + 1] = v.y;
            Bs[r][c4 + 2] = v.z; Bs[r][c4 + 3] = v.w;
        }
        __syncthreads();

#pragma unroll
        for (int kk = 0; kk < 2; kk++) {
            int k = kk * 8;
            float2 bf[4];
#pragma unroll
            for (int nt = 0; nt < 4; nt++) {
                int n = wN * 32 + nt * 8 + g4;
                bf[nt] = make_float2(Bs[n][k + t4], Bs[n][k + t4 + 4]);
            }
#pragma unroll
            for (int mt = 0; mt < 4; mt++) {
                int r = wM * 64 + mt * 16 + g4;
                float4 af = make_float4(As[r][k + t4], As[r + 8][k + t4],
                                        As[r][k + t4 + 4], As[r + 8][k + t4 + 4]);
#pragma unroll
                for (int nt = 0; nt < 4; nt++)
                    mma_tf32(acc[mt][nt], af, bf[nt]);
            }
        }
        __syncthreads();
    }

#pragma unroll
    for (int mt = 0; mt < 4; mt++) {
        int r0 = mBase + wM * 64 + mt * 16 + g4;
        int r1 = r0 + 8;
#pragma unroll
        for (int nt = 0; nt < 4; nt++) {
            int n0 = nBase + wN * 32 + nt * 8 + t4 * 2;
            float2 bv = *(const float2*)(g_b0p + n0);
            *(float2*)(g_G0 + (size_t)r0 * G_ + n0) =
                make_float2(acc[mt][nt][0] + bv.x, acc[mt][nt][1] + bv.y);
            *(float2*)(g_G0 + (size_t)r1 * G_ + n0) =
                make_float2(acc[mt][nt][2] + bv.x, acc[mt][nt][3] + bv.y);
        }
    }
}

// ---------------- persistent recurrent kernel (R6 mainloop, barrier-free steps) ----
// Consumer warps 0..15: ks = w&7 (K-eighth), wm = w>>3 (prow half), full N=64.
// Producer warp 16 (tid 512): issues TMA for 16 K=128 chunks/step into 3 stages.
// Chunks 0..7: {B=h0, A0=Wh0, A1=Wx1}; chunks 8..15: {B=h1, A0slot=Wh1}.
// NEW: no grid barrier. Each CTA posts monotonic group counters after its h
// writes; the producer waits cnt[group(ch)] >= 16*(t+1) before issuing chunk ch.
// Transitivity bounds skew to <1 step, closing the double-buffer WAR hazard.

__global__ void __launch_bounds__(NTHR, 1) lstm_persist(float* __restrict__ out)
{
    extern __shared__ char sm[];
    float* sB = (float*)(sm + SM_BI);
    float* P  = (float*)sm;                       // partial buffer (overlay)
    const uint32_t smBase = (uint32_t)__cvta_generic_to_shared(sm);
    const uint32_t fullB  = smBase + SM_MB;
    const uint32_t emptyB = smBase + SM_MB + 24;

    const int c    = blockIdx.x;
    const int tid  = threadIdx.x;
    const int w    = tid >> 5;
    const int lane = tid & 31;
    const int ks   = w & 7;          // consumer K-eighth
    const int wm   = (w >> 3) & 1;   // prow half
    const int g4   = lane >> 2;
    const int t4   = lane & 3;
    const int v    = tid & 7;        // unit within CTA (consumers)
    const int b    = tid >> 3;       // batch (consumers, <64)
    const int u    = c * 8 + v;
    const int grp  = c >> 4;         // progress group of this CTA
    const int fidx = ((c * 256 + ((b >> 3) * 4 + (v & 3)) * 8 + (b & 7)) << 1) + (v >> 2);

    if (tid == 0) {
#pragma unroll
        for (int s = 0; s < NSTG; s++) {
            mbar_init(fullB  + s * 8, 1);
            mbar_init(emptyB + s * 8, 16);
        }
    }
    if (tid < 32) sB[tid] = g_b1p[c * 32 + tid];
    asm volatile("fence.proxy.async.shared::cta;" ::: "memory");
    __syncthreads();

    float c0r = 0.f, c1r = 0.f;

    // preamble: h0[0] from G0[0] (h=0), zero h1[-1] fragments
    if (tid < NCONS) {
        float* h0w0 = (float*)g_h0F[0];
        float* h1w0 = (float*)g_h1F[0];
        size_t gbase = (size_t)b * G_ + c * 32;
        float gi = g_G0[gbase + v];
        float go = g_G0[gbase + 16 + v];
        float gg = g_G0[gbase + 24 + v];
        float cn = sigmoidf_(gi) * tanhf(gg);
        float hn = sigmoidf_(go) * tanhf(cn);
        c0r = cn;
        h0w0[fidx] = f2tf_f(hn);
        h1w0[fidx] = 0.f;
    }
    __syncthreads();
    if (tid == 0) {
        __threadfence();
        atomicAdd((unsigned*)&g_cnt0[grp], 1u);
        atomicAdd((unsigned*)&g_cnt1[grp], 1u);
    }

    const float4* a0B = g_A0 + (size_t)c * (NCH * 512);
    const float4* a1B = g_A1 + (size_t)c * (NCH * 512);
    const float4* a2B = g_A2 + (size_t)c * (NCH * 512);

    for (int t = 0; t < S_; t++) {
        const float4* bH0 = g_h0F[t & 1];          // h0[t]
        float*        wH0 = (float*)g_h0F[(t + 1) & 1];
        const float4* bH1 = g_h1F[t & 1];          // h1[t-1]
        float*        wH1 = (float*)g_h1F[(t + 1) & 1];

        // consumers: prefetch next layer0's G0 operands
        float p_gi = 0.f, p_gf = 0.f, p_go = 0.f, p_gg = 0.f;
        if (tid < NCONS && t + 1 < S_) {
            size_t gb = ((size_t)(t + 1) * B_ + b) * G_ + c * 32;
            p_gi = g_G0[gb + v];
            p_gf = g_G0[gb + 8 + v];
            p_go = g_G0[gb + 16 + v];
            p_gg = g_G0[gb + 24 + v];
        }

        float acc0[8][4], acc1[8][4];
#pragma unroll
        for (int bt = 0; bt < 8; bt++)
#pragma unroll
            for (int e = 0; e < 4; e++) { acc0[bt][e] = 0.f; acc1[bt][e] = 0.f; }

        if (tid == NCONS) {
            // ---------------- producer ----------------
            const unsigned tgt = 16u * (unsigned)(t + 1);
            for (int ch = 0; ch < 16; ch++) {
                int s = ch % 3, n = ch / 3;
                // data-readiness: wait for the 16-CTA group owning this chunk's h
                if (ch < 8) { while (g_cnt0[ch] < tgt) { } }
                else        { while (g_cnt1[ch - 8] < tgt) { } }
                __threadfence();
                if (t > 0 || ch >= 3) {
                    uint32_t par = (uint32_t)((((s != 0) ? (t & 1) : 0) + n + 1) & 1);
                    mbar_wait(emptyB + s * 8, par);
                }
                uint32_t sb = smBase + (uint32_t)s * STG_SZ;
                uint32_t fb = fullB + s * 8;
                if (ch < 8) {
                    mbar_expect_tx(fb, 65536u);
                    bulk_g2s(sb,          bH0 + (size_t)ch * 2048, 32768, fb);
                    bulk_g2s(sb + 32768,  a0B + (size_t)ch * 1024, 16384, fb);
                    bulk_g2s(sb + 49152,  a1B + (size_t)ch * 1024, 16384, fb);
                } else {
                    int cc = ch - 8;
                    mbar_expect_tx(fb, 49152u);
                    bulk_g2s(sb,          bH1 + (size_t)cc * 2048, 32768, fb);
                    bulk_g2s(sb + 32768,  a2B + (size_t)cc * 1024, 16384, fb);
                }
            }
        } else if (tid < NCONS) {
            // ---------------- consumers ----------------
            // chunks 0..7 : Wh0 -> acc0, Wx1 -> acc1  (B = h0[t])
            for (int ch = 0; ch < 8; ch++) {
                int s = ch % 3, n = ch / 3;
                uint32_t par = (uint32_t)((((s != 0) ? (t & 1) : 0) + n) & 1);
                mbar_wait(fullB + s * 8, par);
                const char* st = sm + s * STG_SZ;
                const float4* A0f = (const float4*)(st + 32768);
                const float4* A1f = (const float4*)(st + 49152);
#pragma unroll
                for (int half = 0; half < 2; half++) {
                    int aidx = half * 512 + (wm * 8 + ks) * 32 + lane;
                    float4 a0 = A0f[aidx];
                    float4 a1 = A1f[aidx];
                    const char* bb = st + (ks + half * 8) * 2048 + t4 * 64 + g4 * 8;
#pragma unroll
                    for (int bt = 0; bt < 8; bt++) {
                        float2 bf = *(const float2*)(bb + bt * 256);
                        mma_tf32(acc0[bt], a0, bf);
                        mma_tf32(acc1[bt], a1, bf);
                    }
                }
                if (lane == 0) mbar_arrive(emptyB + s * 8);
            }
            // chunks 8..15 : Wh1 -> acc1  (B = h1[t-1])
            for (int ch = 8; ch < 16; ch++) {
                int s = ch % 3, n = ch / 3;
                uint32_t par = (uint32_t)((((s != 0) ? (t & 1) : 0) + n) & 1);
                mbar_wait(fullB + s * 8, par);
                const char* st = sm + s * STG_SZ;
                const float4* A0f = (const float4*)(st + 32768);
#pragma unroll
                for (int half = 0; half < 2; half++) {
                    int aidx = half * 512 + (wm * 8 + ks) * 32 + lane;
                    float4 a0 = A0f[aidx];
                    const char* bb = st + (ks + half * 8) * 2048 + t4 * 64 + g4 * 8;
#pragma unroll
                    for (int bt = 0; bt < 8; bt++) {
                        float2 bf = *(const float2*)(bb + bt * 256);
                        mma_tf32(acc1[bt], a0, bf);
                    }
                }
                if (lane == 0) mbar_arrive(emptyB + s * 8);
            }
        }
        __syncthreads();   // all stages consumed; safe to overlay partials

        // ---- write K-split partials (row stride 68 floats, 4352 floats per ks) ----
        if (tid < NCONS) {
            int r0 = wm * 16 + g4;
            int base0 = ks * 4352;
#pragma unroll
            for (int bt = 0; bt < 8; bt++) {
                int col = bt * 8 + t4 * 2;
                *(float2*)&P[base0 + r0 * 68 + col]        = make_float2(acc0[bt][0], acc0[bt][1]);
                *(float2*)&P[base0 + (r0 + 8) * 68 + col]  = make_float2(acc0[bt][2], acc0[bt][3]);
                *(float2*)&P[base0 + 2176 + r0 * 68 + col]       = make_float2(acc1[bt][0], acc1[bt][1]);
                *(float2*)&P[base0 + 2176 + (r0 + 8) * 68 + col] = make_float2(acc1[bt][2], acc1[bt][3]);
            }
        }
        __syncthreads();

        // ---- reduce 8 partials into registers ----
        float g0[4], g1[4];
        if (tid < NCONS) {
#pragma unroll
            for (int q = 0; q < 4; q++) {
                int row = q * 8 + v;
                float s0 = 0.f, s1 = 0.f;
#pragma unroll
                for (int kr = 0; kr < 8; kr++) {
                    s0 += P[kr * 4352 + row * 68 + b];
                    s1 += P[kr * 4352 + 2176 + row * 68 + b];
                }
                g0[q] = s0; g1[q] = s1;
            }
        }
        __syncthreads();   // P dead -> producer may start refilling stages next iter

        // ---- cell epilogues ----
        if (tid < NCONS) {
            // layer 1 step t
            {
                float gi = g1[0] + sB[v];
                float gf = g1[1] + sB[8 + v];
                float go = g1[2] + sB[16 + v];
                float gg = g1[3] + sB[24 + v];
                float cn = sigmoidf_(gf) * c1r + sigmoidf_(gi) * tanhf(gg);
                float hn = sigmoidf_(go) * tanhf(cn);
                c1r = cn;
                out[((size_t)b * S_ + t) * H_ + u] = hn;
                wH1[fidx] = f2tf_f(hn);
                if (t == S_ - 1) {
                    out[(size_t)OUT_ELEMS + 1ull * BH_ + (size_t)b * H_ + u] = hn;
                    out[(size_t)OUT_ELEMS + 3ull * BH_ + (size_t)b * H_ + u] = cn;
                }
            }
            // layer 0 step t+1
            if (t < S_ - 1) {
                float gi = g0[0] + p_gi;
                float gf = g0[1] + p_gf;
                float go = g0[2] + p_go;
                float gg = g0[3] + p_gg;
                float cn = sigmoidf_(gf) * c0r + sigmoidf_(gi) * tanhf(gg);
                float hn = sigmoidf_(go) * tanhf(cn);
                c0r = cn;
                wH0[fidx] = f2tf_f(hn);
                if (t == S_ - 2) {
                    out[(size_t)OUT_ELEMS + (size_t)b * H_ + u]              = hn;
                    out[(size_t)OUT_ELEMS + 2ull * BH_ + (size_t)b * H_ + u] = cn;
                }
            }
        }
        // post progress: h0[t+1] and h1[t] written by this CTA
        __syncthreads();
        if (tid == 0 && t + 1 < S_) {
            __threadfence();
            atomicAdd((unsigned*)&g_cnt0[grp], 1u);
            atomicAdd((unsigned*)&g_cnt1[grp], 1u);
        }
    }
}

// ---------------- launch ----------------
extern "C" void kernel_launch(void* const* d_in, const int* in_sizes, int n_in,
                              void* d_out, int out_size)
{
    const float* x   = (const float*)d_in[0];
    const float* Wx0 = (const float*)d_in[1];
    const float* Wh0 = (const float*)d_in[2];
    const float* bx0 = (const float*)d_in[3];
    const float* bh0 = (const float*)d_in[4];
    const float* Wx1 = (const float*)d_in[5];
    const float* Wh1 = (const float*)d_in[6];
    const float* bx1 = (const float*)d_in[7];
    const float* bh1 = (const float*)d_in[8];
    float* out = (float*)d_out;

    static bool attr_done = false;
    if (!attr_done) {
        cudaFuncSetAttribute(lstm_persist,
                             cudaFuncAttributeMaxDynamicSharedMemorySize, SM_TOT);
        attr_done = true;
    }

    convert_all<<<4096, 256>>>(Wx0, Wh0, Wx1, Wh1, bx0, bh0, bx1, bh1);
    precompute_kernel<<<dim3(G_ / 128, (S_ * B_) / 128), 256>>>(x);
    lstm_persist<<<NCTA, NTHR, SM_TOT>>>(out);
}

// round 12
// speedup vs baseline: 1.0878x; 1.0878x over previous
#include <cuda_runtime.h>
#include <cstdint>

// Problem dims
#define B_  64
#define S_  512
#define I_  512
#define H_  1024
#define G_  4096          // 4*H
#define BH_ (B_*H_)       // 65536
#define OUT_ELEMS (B_*S_*H_)   // 33554432

#define NCTA  128
#define NTHR  544         // 512 consumers + 32 producer warp
#define NCONS 512
#define NCH   16          // K-chunks of 64 per 1024-wide matrix (storage layout)

// persistent-kernel smem plan
// 3 stages x 64KB: [0,32768) B(h), [32768,49152) A0, [49152,65536) A1
// partial-sum buffer overlays stage area after consumption: 8 x 17408B
#define STG_SZ 65536
#define NSTG   3
#define SM_BI  196608
#define SM_MB  196736     // full[3] @ +0, empty[3] @ +24
#define SM_TOT 196800

// ---------------- device scratch (static, allowed) ----------------
__device__ float  g_Wx0p[G_*I_];            // tf32-rounded, gate-permuted rows (for precompute)
__device__ float  g_b0p[G_];                // bx0+bh0, permuted (folded into G0)
__device__ float  g_b1p[G_];                // bx1+bh1, permuted
__device__ float4 g_A0[(size_t)NCTA*NCH*512];  // Wh0 fragment-major
__device__ float4 g_A1[(size_t)NCTA*NCH*512];  // Wx1
__device__ float4 g_A2[(size_t)NCTA*NCH*512];  // Wh1
__device__ float  g_G0[(size_t)S_*B_*G_];   // x-path preactivations [t][b][prow] (512MB)
__device__ float4 g_h0F[2][16384];          // h0 fragment-major, double buffered
__device__ float4 g_h1F[2][16384];          // h1 fragment-major
__device__ unsigned g_barCount;
__device__ volatile unsigned g_barGen;

// ---------------- helpers ----------------
__device__ __forceinline__ float f2tf_f(float f) {
    uint32_t r;
    asm("cvt.rna.tf32.f32 %0, %1;" : "=r"(r) : "f"(f));
    return __uint_as_float(r);
}

__device__ __forceinline__ void mma_tf32(float* d, float4 a, float2 b) {
    asm volatile(
        "mma.sync.aligned.m16n8k8.row.col.f32.tf32.tf32.f32 "
        "{%0,%1,%2,%3}, {%4,%5,%6,%7}, {%8,%9}, {%0,%1,%2,%3};\n"
        : "+f"(d[0]), "+f"(d[1]), "+f"(d[2]), "+f"(d[3])
        : "r"(__float_as_uint(a.x)), "r"(__float_as_uint(a.y)),
          "r"(__float_as_uint(a.z)), "r"(__float_as_uint(a.w)),
          "r"(__float_as_uint(b.x)), "r"(__float_as_uint(b.y)));
}

__device__ __forceinline__ float sigmoidf_(float x) { return 1.0f / (1.0f + expf(-x)); }

// ---- TMA bulk + mbarrier machinery ----
__device__ __forceinline__ void mbar_init(uint32_t addr, uint32_t count) {
    asm volatile("mbarrier.init.shared.b64 [%0], %1;" :: "r"(addr), "r"(count) : "memory");
}
__device__ __forceinline__ void mbar_expect_tx(uint32_t addr, uint32_t bytes) {
    asm volatile("mbarrier.arrive.expect_tx.shared.b64 _, [%0], %1;"
                 :: "r"(addr), "r"(bytes) : "memory");
}
__device__ __forceinline__ void mbar_arrive(uint32_t addr) {
    asm volatile("mbarrier.arrive.shared.b64 _, [%0];" :: "r"(addr) : "memory");
}
__device__ __forceinline__ void bulk_g2s(uint32_t dst, const void* src,
                                         uint32_t bytes, uint32_t mbar) {
    asm volatile(
        "cp.async.bulk.shared::cta.global.mbarrier::complete_tx::bytes [%0], [%1], %2, [%3];"
        :: "r"(dst), "l"(src), "r"(bytes), "r"(mbar) : "memory");
}
__device__ __forceinline__ void mbar_wait(uint32_t mbar, uint32_t parity) {
    asm volatile(
        "{\n\t"
        ".reg .pred P;\n\t"
        "WAIT_LOOP_%=:\n\t"
        "mbarrier.try_wait.parity.acquire.cta.shared::cta.b64 P, [%0], %1, 0x989680;\n\t"
        "@P bra.uni WAIT_DONE_%=;\n\t"
        "bra.uni WAIT_LOOP_%=;\n\t"
        "WAIT_DONE_%=:\n\t"
        "}"
        :: "r"(mbar), "r"(parity) : "memory");
}

// grid barrier (all NCTA CTAs co-resident) — R6 proven atomic version
__device__ __forceinline__ void gsync() {
    __syncthreads();
    if (threadIdx.x == 0) {
        unsigned gen = g_barGen;
        __threadfence();
        if (atomicAdd(&g_barCount, 1u) == NCTA - 1) {
            g_barCount = 0;
            __threadfence();
            g_barGen = gen + 1;
        } else {
            while (g_barGen == gen) { }
            __threadfence();
        }
    }
    __syncthreads();
}

// Row permutation: prow = (u/8)*32 + q*8 + (u%8); CTA c owns units [8c,8c+8).

// ---------------- convert: natural Wx0 + biases ----------------
__global__ void __launch_bounds__(256) convert_nat(
    const float* __restrict__ Wx0, const float* __restrict__ bx0, const float* __restrict__ bh0,
    const float* __restrict__ bx1, const float* __restrict__ bh1)
{
    const int total = G_ * I_;
    for (int i = blockIdx.x * blockDim.x + threadIdx.x; i < total;
         i += gridDim.x * blockDim.x) {
        int prow = i / I_;
        int k    = i - prow * I_;
        int u    = ((prow >> 5) << 3) + (prow & 7);
        int q    = (prow >> 3) & 3;
        int orig = q * H_ + u;
        g_Wx0p[i] = f2tf_f(Wx0[(size_t)orig * I_ + k]);
        if (k == 0) {
            g_b0p[prow] = bx0[orig] + bh0[orig];
            g_b1p[prow] = bx1[orig] + bh1[orig];
        }
    }
}

// ---------------- convert: fragment-major recurrent weights ----------------
__global__ void __launch_bounds__(256) convert_frag(
    const float* __restrict__ Wh0, const float* __restrict__ Wx1, const float* __restrict__ Wh1)
{
    const int total = NCTA * NCH * 512;
    for (int idx = blockIdx.x * blockDim.x + threadIdx.x; idx < total;
         idx += gridDim.x * blockDim.x) {
        int lane = idx & 31;
        int kk   = (idx >> 5) & 7;
        int wm   = (idx >> 8) & 1;
        int ch   = (idx >> 9) & 15;
        int c    = idx >> 13;
        int g4 = lane >> 2, t4 = lane & 3;
        int p0 = wm * 16 + g4;
        int q0 = p0 >> 3, v = p0 & 7;
        int o0 = q0 * H_ + c * 8 + v;
        int k  = ch * 64 + kk * 8 + t4;
        size_t r0 = (size_t)o0 * H_ + k;
        size_t r1 = r0 + (size_t)H_ * H_;
        g_A0[idx] = make_float4(f2tf_f(Wh0[r0]), f2tf_f(Wh0[r1]),
                                f2tf_f(Wh0[r0 + 4]), f2tf_f(Wh0[r1 + 4]));
        g_A1[idx] = make_float4(f2tf_f(Wx1[r0]), f2tf_f(Wx1[r1]),
                                f2tf_f(Wx1[r0 + 4]), f2tf_f(Wx1[r1 + 4]));
        g_A2[idx] = make_float4(f2tf_f(Wh1[r0]), f2tf_f(Wh1[r1]),
                                f2tf_f(Wh1[r0 + 4]), f2tf_f(Wh1[r1 + 4]));
    }
}

// ---------------- init (every replay): barrier state only ----------------
__global__ void init_kernel() {
    if (threadIdx.x == 0) { g_barCount = 0; g_barGen = 0; }
}

// ---------------- x-path precompute: G0 = x@Wx0p^T + b0p ----------------
__global__ void __launch_bounds__(256, 1) precompute_kernel(const float* __restrict__ x)
{
    __shared__ float As[128][20];
    __shared__ float Bs[128][20];

    const int tid  = threadIdx.x;
    const int w    = tid >> 5;
    const int lane = tid & 31;
    const int wM   = w >> 2;
    const int wN   = w & 3;
    const int mBase = blockIdx.y * 128;
    const int nBase = blockIdx.x * 128;
    const int g4 = lane >> 2;
    const int t4 = lane & 3;

    float acc[4][4][4];
#pragma unroll
    for (int mt = 0; mt < 4; mt++)
#pragma unroll
        for (int nt = 0; nt < 4; nt++)
#pragma unroll
            for (int e = 0; e < 4; e++) acc[mt][nt][e] = 0.0f;

    for (int kc = 0; kc < I_; kc += 16) {
#pragma unroll
        for (int it = 0; it < 2; it++) {
            int i  = tid + it * 256;
            int r  = i >> 2;
            int c4 = (i & 3) * 4;
            int m  = mBase + r;
            int tt = m >> 6;
            int bb = m & 63;
            float4 v = *(const float4*)(x + ((size_t)bb * S_ + tt) * I_ + kc + c4);
            As[r][c4 + 0] = f2tf_f(v.x); As[r][c4 + 1] = f2tf_f(v.y);
            As[r][c4 + 2] = f2tf_f(v.z); As[r][c4 + 3] = f2tf_f(v.w);
        }
#pragma unroll
        for (int it = 0; it < 2; it++) {
            int i  = tid + it * 256;
            int r  = i >> 2;
            int c4 = (i & 3) * 4;
            float4 v = *(const float4*)(g_Wx0p + (size_t)(nBase + r) * I_ + kc + c4);
            Bs[r][c4 + 0] = v.x; Bs[r][c4 + 1] = v.y;
            Bs[r][c4 + 2] = v.z; Bs[r][c4 + 3] = v.w;
        }
        __syncthreads();

#pragma unroll
        for (int kk = 0; kk < 2; kk++) {
            int k = kk * 8;
            float2 bf[4];
#pragma unroll
            for (int nt = 0; nt < 4; nt++) {
                int n = wN * 32 + nt * 8 + g4;
                bf[nt] = make_float2(Bs[n][k + t4], Bs[n][k + t4 + 4]);
            }
#pragma unroll
            for (int mt = 0; mt < 4; mt++) {
                int r = wM * 64 + mt * 16 + g4;
                float4 af = make_float4(As[r][k + t4], As[r + 8][k + t4],
                                        As[r][k + t4 + 4], As[r + 8][k + t4 + 4]);
#pragma unroll
                for (int nt = 0; nt < 4; nt++)
                    mma_tf32(acc[mt][nt], af, bf[nt]);
            }
        }
        __syncthreads();
    }

#pragma unroll
    for (int mt = 0; mt < 4; mt++) {
        int r0 = mBase + wM * 64 + mt * 16 + g4;
        int r1 = r0 + 8;
#pragma unroll
        for (int nt = 0; nt < 4; nt++) {
            int n0 = nBase + wN * 32 + nt * 8 + t4 * 2;
            float2 bv = *(const float2*)(g_b0p + n0);
            *(float2*)(g_G0 + (size_t)r0 * G_ + n0) =
                make_float2(acc[mt][nt][0] + bv.x, acc[mt][nt][1] + bv.y);
            *(float2*)(g_G0 + (size_t)r1 * G_ + n0) =
                make_float2(acc[mt][nt][2] + bv.x, acc[mt][nt][3] + bv.y);
        }
    }
}

// ---------------- persistent recurrent kernel (R6 + per-CTA chunk rotation) ----
// Consumer warps 0..15: ks = w&7 (K-eighth), wm = w>>3 (prow half), full N=64.
// Producer warp 16 (tid 512): issues TMA for 16 K=128 chunks/step into 3 stages.
// Positions 0..7: {B=h0, A0=Wh0, A1=Wx1}; positions 8..15: {B=h1, A0slot=Wh1}.
// NEW (only change vs R6): chunk id visited at position p is rotated per CTA:
// q = (p + (c&7)) & 7 — spreads simultaneous h reads across the whole h range
// (concurrent readers per chunk: 128 -> 16), de-hotspotting L2 slices.
// Consumers are chunk-id agnostic; accumulation order change is ±ulp only.

__global__ void __launch_bounds__(NTHR, 1) lstm_persist(float* __restrict__ out)
{
    extern __shared__ char sm[];
    float* sB = (float*)(sm + SM_BI);
    float* P  = (float*)sm;                       // partial buffer (overlay)
    const uint32_t smBase = (uint32_t)__cvta_generic_to_shared(sm);
    const uint32_t fullB  = smBase + SM_MB;
    const uint32_t emptyB = smBase + SM_MB + 24;

    const int c    = blockIdx.x;
    const int tid  = threadIdx.x;
    const int w    = tid >> 5;
    const int lane = tid & 31;
    const int ks   = w & 7;          // consumer K-eighth
    const int wm   = (w >> 3) & 1;   // prow half
    const int g4   = lane >> 2;
    const int t4   = lane & 3;
    const int v    = tid & 7;        // unit within CTA (consumers)
    const int b    = tid >> 3;       // batch (consumers, <64)
    const int u    = c * 8 + v;
    const int rot  = c & 7;          // per-CTA chunk rotation
    const int fidx = ((c * 256 + ((b >> 3) * 4 + (v & 3)) * 8 + (b & 7)) << 1) + (v >> 2);

    if (tid == 0) {
#pragma unroll
        for (int s = 0; s < NSTG; s++) {
            mbar_init(fullB  + s * 8, 1);
            mbar_init(emptyB + s * 8, 16);
        }
    }
    if (tid < 32) sB[tid] = g_b1p[c * 32 + tid];
    asm volatile("fence.proxy.async.shared::cta;" ::: "memory");
    __syncthreads();

    float c0r = 0.f, c1r = 0.f;

    // preamble: h0[0] from G0[0] (h=0), zero h1[-1] fragments
    if (tid < NCONS) {
        float* h0w0 = (float*)g_h0F[0];
        float* h1w0 = (float*)g_h1F[0];
        size_t gbase = (size_t)b * G_ + c * 32;
        float gi = g_G0[gbase + v];
        float go = g_G0[gbase + 16 + v];
        float gg = g_G0[gbase + 24 + v];
        float cn = sigmoidf_(gi) * tanhf(gg);
        float hn = sigmoidf_(go) * tanhf(cn);
        c0r = cn;
        h0w0[fidx] = f2tf_f(hn);
        h1w0[fidx] = 0.f;
    }
    gsync();

    const float4* a0B = g_A0 + (size_t)c * (NCH * 512);
    const float4* a1B = g_A1 + (size_t)c * (NCH * 512);
    const float4* a2B = g_A2 + (size_t)c * (NCH * 512);

    for (int t = 0; t < S_; t++) {
        const float4* bH0 = g_h0F[t & 1];          // h0[t]
        float*        wH0 = (float*)g_h0F[(t + 1) & 1];
        const float4* bH1 = g_h1F[t & 1];          // h1[t-1]
        float*        wH1 = (float*)g_h1F[(t + 1) & 1];

        // consumers: prefetch next layer0's G0 operands
        float p_gi = 0.f, p_gf = 0.f, p_go = 0.f, p_gg = 0.f;
        if (tid < NCONS && t + 1 < S_) {
            size_t gb = ((size_t)(t + 1) * B_ + b) * G_ + c * 32;
            p_gi = g_G0[gb + v];
            p_gf = g_G0[gb + 8 + v];
            p_go = g_G0[gb + 16 + v];
            p_gg = g_G0[gb + 24 + v];
        }

        float acc0[8][4], acc1[8][4];
#pragma unroll
        for (int bt = 0; bt < 8; bt++)
#pragma unroll
            for (int e = 0; e < 4; e++) { acc0[bt][e] = 0.f; acc1[bt][e] = 0.f; }

        if (tid == NCONS) {
            // ---------------- producer ----------------
            for (int ch = 0; ch < 16; ch++) {
                int s = ch % 3, n = ch / 3;
                if (t > 0 || ch >= 3) {
                    uint32_t par = (uint32_t)((((s != 0) ? (t & 1) : 0) + n + 1) & 1);
                    mbar_wait(emptyB + s * 8, par);
                }
                uint32_t sb = smBase + (uint32_t)s * STG_SZ;
                uint32_t fb = fullB + s * 8;
                if (ch < 8) {
                    int q = (ch + rot) & 7;           // rotated chunk id
                    mbar_expect_tx(fb, 65536u);
                    bulk_g2s(sb,          bH0 + (size_t)q * 2048, 32768, fb);
                    bulk_g2s(sb + 32768,  a0B + (size_t)q * 1024, 16384, fb);
                    bulk_g2s(sb + 49152,  a1B + (size_t)q * 1024, 16384, fb);
                } else {
                    int q = (ch - 8 + rot) & 7;       // rotated chunk id
                    mbar_expect_tx(fb, 49152u);
                    bulk_g2s(sb,          bH1 + (size_t)q * 2048, 32768, fb);
                    bulk_g2s(sb + 32768,  a2B + (size_t)q * 1024, 16384, fb);
                }
            }
        } else if (tid < NCONS) {
            // ---------------- consumers (chunk-id agnostic) ----------------
            // positions 0..7 : Wh0 -> acc0, Wx1 -> acc1  (B = h0[t])
            for (int ch = 0; ch < 8; ch++) {
                int s = ch % 3, n = ch / 3;
                uint32_t par = (uint32_t)((((s != 0) ? (t & 1) : 0) + n) & 1);
                mbar_wait(fullB + s * 8, par);
                const char* st = sm + s * STG_SZ;
                const float4* A0f = (const float4*)(st + 32768);
                const float4* A1f = (const float4*)(st + 49152);
#pragma unroll
                for (int half = 0; half < 2; half++) {
                    int aidx = half * 512 + (wm * 8 + ks) * 32 + lane;
                    float4 a0 = A0f[aidx];
                    float4 a1 = A1f[aidx];
                    const char* bb = st + (ks + half * 8) * 2048 + t4 * 64 + g4 * 8;
#pragma unroll
                    for (int bt = 0; bt < 8; bt++) {
                        float2 bf = *(const float2*)(bb + bt * 256);
                        mma_tf32(acc0[bt], a0, bf);
                        mma_tf32(acc1[bt], a1, bf);
                    }
                }
                if (lane == 0) mbar_arrive(emptyB + s * 8);
            }
            // positions 8..15 : Wh1 -> acc1  (B = h1[t-1])
            for (int ch = 8; ch < 16; ch++) {
                int s = ch % 3, n = ch / 3;
                uint32_t par = (uint32_t)((((s != 0) ? (t & 1) : 0) + n) & 1);
                mbar_wait(fullB + s * 8, par);
                const char* st = sm + s * STG_SZ;
                const float4* A0f = (const float4*)(st + 32768);
#pragma unroll
                for (int half = 0; half < 2; half++) {
                    int aidx = half * 512 + (wm * 8 + ks) * 32 + lane;
                    float4 a0 = A0f[aidx];
                    const char* bb = st + (ks + half * 8) * 2048 + t4 * 64 + g4 * 8;
#pragma unroll
                    for (int bt = 0; bt < 8; bt++) {
                        float2 bf = *(const float2*)(bb + bt * 256);
                        mma_tf32(acc1[bt], a0, bf);
                    }
                }
                if (lane == 0) mbar_arrive(emptyB + s * 8);
            }
        }
        __syncthreads();   // all stages consumed; safe to overlay partials

        // ---- write K-split partials (row stride 68 floats, 4352 floats per ks) ----
        if (tid < NCONS) {
            int r0 = wm * 16 + g4;
            int base0 = ks * 4352;
#pragma unroll
            for (int bt = 0; bt < 8; bt++) {
                int col = bt * 8 + t4 * 2;
                *(float2*)&P[base0 + r0 * 68 + col]        = make_float2(acc0[bt][0], acc0[bt][1]);
                *(float2*)&P[base0 + (r0 + 8) * 68 + col]  = make_float2(acc0[bt][2], acc0[bt][3]);
                *(float2*)&P[base0 + 2176 + r0 * 68 + col]       = make_float2(acc1[bt][0], acc1[bt][1]);
                *(float2*)&P[base0 + 2176 + (r0 + 8) * 68 + col] = make_float2(acc1[bt][2], acc1[bt][3]);
            }
        }
        __syncthreads();

        // ---- reduce 8 partials + cell epilogues ----
        if (tid < NCONS) {
            float g0[4], g1[4];
#pragma unroll
            for (int q = 0; q < 4; q++) {
                int row = q * 8 + v;
                float s0 = 0.f, s1 = 0.f;
#pragma unroll
                for (int kr = 0; kr < 8; kr++) {
                    s0 += P[kr * 4352 + row * 68 + b];
                    s1 += P[kr * 4352 + 2176 + row * 68 + b];
                }
                g0[q] = s0; g1[q] = s1;
            }
            // layer 1 step t
            {
                float gi = g1[0] + sB[v];
                float gf = g1[1] + sB[8 + v];
                float go = g1[2] + sB[16 + v];
                float gg = g1[3] + sB[24 + v];
                float cn = sigmoidf_(gf) * c1r + sigmoidf_(gi) * tanhf(gg);
                float hn = sigmoidf_(go) * tanhf(cn);
                c1r = cn;
                out[((size_t)b * S_ + t) * H_ + u] = hn;
                wH1[fidx] = f2tf_f(hn);
                if (t == S_ - 1) {
                    out[(size_t)OUT_ELEMS + 1ull * BH_ + (size_t)b * H_ + u] = hn;
                    out[(size_t)OUT_ELEMS + 3ull * BH_ + (size_t)b * H_ + u] = cn;
                }
            }
            // layer 0 step t+1
            if (t < S_ - 1) {
                float gi = g0[0] + p_gi;
                float gf = g0[1] + p_gf;
                float go = g0[2] + p_go;
                float gg = g0[3] + p_gg;
                float cn = sigmoidf_(gf) * c0r + sigmoidf_(gi) * tanhf(gg);
                float hn = sigmoidf_(go) * tanhf(cn);
                c0r = cn;
                wH0[fidx] = f2tf_f(hn);
                if (t == S_ - 2) {
                    out[(size_t)OUT_ELEMS + (size_t)b * H_ + u]              = hn;
                    out[(size_t)OUT_ELEMS + 2ull * BH_ + (size_t)b * H_ + u] = cn;
                }
            }
        }
        if (t + 1 < S_) gsync();
    }
}

// ---------------- launch ----------------
extern "C" void kernel_launch(void* const* d_in, const int* in_sizes, int n_in,
                              void* d_out, int out_size)
{
    const float* x   = (const float*)d_in[0];
    const float* Wx0 = (const float*)d_in[1];
    const float* Wh0 = (const float*)d_in[2];
    const float* bx0 = (const float*)d_in[3];
    const float* bh0 = (const float*)d_in[4];
    const float* Wx1 = (const float*)d_in[5];
    const float* Wh1 = (const float*)d_in[6];
    const float* bx1 = (const float*)d_in[7];
    const float* bh1 = (const float*)d_in[8];
    float* out = (float*)d_out;

    static bool attr_done = false;
    if (!attr_done) {
        cudaFuncSetAttribute(lstm_persist,
                             cudaFuncAttributeMaxDynamicSharedMemorySize, SM_TOT);
        attr_done = true;
    }

    convert_nat<<<2048, 256>>>(Wx0, bx0, bh0, bx1, bh1);
    convert_frag<<<4096, 256>>>(Wh0, Wx1, Wh1);
    init_kernel<<<1, 32>>>();
    precompute_kernel<<<dim3(G_ / 128, (S_ * B_) / 128), 256>>>(x);
    lstm_persist<<<NCTA, NTHR, SM_TOT>>>(out);
}

// round 13
// speedup vs baseline: 1.2132x; 1.1152x over previous
#include <cuda_runtime.h>
#include <cuda_fp16.h>
#include <cstdint>

// Problem dims
#define B_  64
#define S_  512
#define I_  512
#define H_  1024
#define G_  4096          // 4*H
#define BH_ (B_*H_)       // 65536
#define OUT_ELEMS (B_*S_*H_)   // 33554432

#define NCTA  128
#define NTHR  544         // 512 consumers + 32 producer warp
#define NCONS 512
#define NCH   16          // K-chunks of 64 per 1024-wide matrix (storage layout)

// persistent-kernel smem plan (fp16 h staging)
// 3 stages x 48KB: [0,16384) B(h, fp16), [16384,32768) A0, [32768,49152) A1
// partial-sum buffer (139264 B) overlays the 147456 B stage area after consumption
#define STG_SZ 49152
#define NSTG   3
#define SM_BI  147456
#define SM_MB  147584     // full[3] @ +0, empty[3] @ +24
#define SM_TOT 147712

// ---------------- device scratch (static, allowed) ----------------
__device__ float  g_Wx0p[G_*I_];            // tf32-rounded, gate-permuted rows (for precompute)
__device__ float  g_b0p[G_];                // bx0+bh0, permuted (folded into G0)
__device__ float  g_b1p[G_];                // bx1+bh1, permuted
__device__ float4 g_A0[(size_t)NCTA*NCH*512];  // Wh0 fragment-major
__device__ float4 g_A1[(size_t)NCTA*NCH*512];  // Wx1
__device__ float4 g_A2[(size_t)NCTA*NCH*512];  // Wh1
__device__ float  g_G0[(size_t)S_*B_*G_];   // x-path preactivations [t][b][prow] (512MB)
__device__ __half g_h0I[2][65536];          // h0 fragment-major fp16, double buffered (128KB)
__device__ __half g_h1I[2][65536];          // h1 fragment-major fp16
__device__ unsigned g_barCount;
__device__ volatile unsigned g_barGen;

// ---------------- helpers ----------------
__device__ __forceinline__ float f2tf_f(float f) {
    uint32_t r;
    asm("cvt.rna.tf32.f32 %0, %1;" : "=r"(r) : "f"(f));
    return __uint_as_float(r);
}

__device__ __forceinline__ void mma_tf32(float* d, float4 a, float2 b) {
    asm volatile(
        "mma.sync.aligned.m16n8k8.row.col.f32.tf32.tf32.f32 "
        "{%0,%1,%2,%3}, {%4,%5,%6,%7}, {%8,%9}, {%0,%1,%2,%3};\n"
        : "+f"(d[0]), "+f"(d[1]), "+f"(d[2]), "+f"(d[3])
        : "r"(__float_as_uint(a.x)), "r"(__float_as_uint(a.y)),
          "r"(__float_as_uint(a.z)), "r"(__float_as_uint(a.w)),
          "r"(__float_as_uint(b.x)), "r"(__float_as_uint(b.y)));
}

__device__ __forceinline__ float sigmoidf_(float x) { return 1.0f / (1.0f + expf(-x)); }

// ---- TMA bulk + mbarrier machinery ----
__device__ __forceinline__ void mbar_init(uint32_t addr, uint32_t count) {
    asm volatile("mbarrier.init.shared.b64 [%0], %1;" :: "r"(addr), "r"(count) : "memory");
}
__device__ __forceinline__ void mbar_expect_tx(uint32_t addr, uint32_t bytes) {
    asm volatile("mbarrier.arrive.expect_tx.shared.b64 _, [%0], %1;"
                 :: "r"(addr), "r"(bytes) : "memory");
}
__device__ __forceinline__ void mbar_arrive(uint32_t addr) {
    asm volatile("mbarrier.arrive.shared.b64 _, [%0];" :: "r"(addr) : "memory");
}
__device__ __forceinline__ void bulk_g2s(uint32_t dst, const void* src,
                                         uint32_t bytes, uint32_t mbar) {
    asm volatile(
        "cp.async.bulk.shared::cta.global.mbarrier::complete_tx::bytes [%0], [%1], %2, [%3];"
        :: "r"(dst), "l"(src), "r"(bytes), "r"(mbar) : "memory");
}
__device__ __forceinline__ void mbar_wait(uint32_t mbar, uint32_t parity) {
    asm volatile(
        "{\n\t"
        ".reg .pred P;\n\t"
        "WAIT_LOOP_%=:\n\t"
        "mbarrier.try_wait.parity.acquire.cta.shared::cta.b64 P, [%0], %1, 0x989680;\n\t"
        "@P bra.uni WAIT_DONE_%=;\n\t"
        "bra.uni WAIT_LOOP_%=;\n\t"
        "WAIT_DONE_%=:\n\t"
        "}"
        :: "r"(mbar), "r"(parity) : "memory");
}

// grid barrier (all NCTA CTAs co-resident) — proven atomic version
__device__ __forceinline__ void gsync() {
    __syncthreads();
    if (threadIdx.x == 0) {
        unsigned gen = g_barGen;
        __threadfence();
        if (atomicAdd(&g_barCount, 1u) == NCTA - 1) {
            g_barCount = 0;
            __threadfence();
            g_barGen = gen + 1;
        } else {
            while (g_barGen == gen) { }
            __threadfence();
        }
    }
    __syncthreads();
}

// Row permutation: prow = (u/8)*32 + q*8 + (u%8); CTA c owns units [8c,8c+8).

// ---------------- convert: natural Wx0 + biases ----------------
__global__ void __launch_bounds__(256) convert_nat(
    const float* __restrict__ Wx0, const float* __restrict__ bx0, const float* __restrict__ bh0,
    const float* __restrict__ bx1, const float* __restrict__ bh1)
{
    const int total = G_ * I_;
    for (int i = blockIdx.x * blockDim.x + threadIdx.x; i < total;
         i += gridDim.x * blockDim.x) {
        int prow = i / I_;
        int k    = i - prow * I_;
        int u    = ((prow >> 5) << 3) + (prow & 7);
        int q    = (prow >> 3) & 3;
        int orig = q * H_ + u;
        g_Wx0p[i] = f2tf_f(Wx0[(size_t)orig * I_ + k]);
        if (k == 0) {
            g_b0p[prow] = bx0[orig] + bh0[orig];
            g_b1p[prow] = bx1[orig] + bh1[orig];
        }
    }
}

// ---------------- convert: fragment-major recurrent weights ----------------
__global__ void __launch_bounds__(256) convert_frag(
    const float* __restrict__ Wh0, const float* __restrict__ Wx1, const float* __restrict__ Wh1)
{
    const int total = NCTA * NCH * 512;
    for (int idx = blockIdx.x * blockDim.x + threadIdx.x; idx < total;
         idx += gridDim.x * blockDim.x) {
        int lane = idx & 31;
        int kk   = (idx >> 5) & 7;
        int wm   = (idx >> 8) & 1;
        int ch   = (idx >> 9) & 15;
        int c    = idx >> 13;
        int g4 = lane >> 2, t4 = lane & 3;
        int p0 = wm * 16 + g4;
        int q0 = p0 >> 3, v = p0 & 7;
        int o0 = q0 * H_ + c * 8 + v;
        int k  = ch * 64 + kk * 8 + t4;
        size_t r0 = (size_t)o0 * H_ + k;
        size_t r1 = r0 + (size_t)H_ * H_;
        g_A0[idx] = make_float4(f2tf_f(Wh0[r0]), f2tf_f(Wh0[r1]),
                                f2tf_f(Wh0[r0 + 4]), f2tf_f(Wh0[r1 + 4]));
        g_A1[idx] = make_float4(f2tf_f(Wx1[r0]), f2tf_f(Wx1[r1]),
                                f2tf_f(Wx1[r0 + 4]), f2tf_f(Wx1[r1 + 4]));
        g_A2[idx] = make_float4(f2tf_f(Wh1[r0]), f2tf_f(Wh1[r1]),
                                f2tf_f(Wh1[r0 + 4]), f2tf_f(Wh1[r1 + 4]));
    }
}

// ---------------- init (every replay): barrier state only ----------------
__global__ void init_kernel() {
    if (threadIdx.x == 0) { g_barCount = 0; g_barGen = 0; }
}

// ---------------- x-path precompute: G0 = x@Wx0p^T + b0p ----------------
__global__ void __launch_bounds__(256, 1) precompute_kernel(const float* __restrict__ x)
{
    __shared__ float As[128][20];
    __shared__ float Bs[128][20];

    const int tid  = threadIdx.x;
    const int w    = tid >> 5;
    const int lane = tid & 31;
    const int wM   = w >> 2;
    const int wN   = w & 3;
    const int mBase = blockIdx.y * 128;
    const int nBase = blockIdx.x * 128;
    const int g4 = lane >> 2;
    const int t4 = lane & 3;

    float acc[4][4][4];
#pragma unroll
    for (int mt = 0; mt < 4; mt++)
#pragma unroll
        for (int nt = 0; nt < 4; nt++)
#pragma unroll
            for (int e = 0; e < 4; e++) acc[mt][nt][e] = 0.0f;

    for (int kc = 0; kc < I_; kc += 16) {
#pragma unroll
        for (int it = 0; it < 2; it++) {
            int i  = tid + it * 256;
            int r  = i >> 2;
            int c4 = (i & 3) * 4;
            int m  = mBase + r;
            int tt = m >> 6;
            int bb = m & 63;
            float4 v = *(const float4*)(x + ((size_t)bb * S_ + tt) * I_ + kc + c4);
            As[r][c4 + 0] = f2tf_f(v.x); As[r][c4 + 1] = f2tf_f(v.y);
            As[r][c4 + 2] = f2tf_f(v.z); As[r][c4 + 3] = f2tf_f(v.w);
        }
#pragma unroll
        for (int it = 0; it < 2; it++) {
            int i  = tid + it * 256;
            int r  = i >> 2;
            int c4 = (i & 3) * 4;
            float4 v = *(const float4*)(g_Wx0p + (size_t)(nBase + r) * I_ + kc + c4);
            Bs[r][c4 + 0] = v.x; Bs[r][c4 + 1] = v.y;
            Bs[r][c4 + 2] = v.z; Bs[r][c4 + 3] = v.w;
        }
        __syncthreads();

#pragma unroll
        for (int kk = 0; kk < 2; kk++) {
            int k = kk * 8;
            float2 bf[4];
#pragma unroll
            for (int nt = 0; nt < 4; nt++) {
                int n = wN * 32 + nt * 8 + g4;
                bf[nt] = make_float2(Bs[n][k + t4], Bs[n][k + t4 + 4]);
            }
#pragma unroll
            for (int mt = 0; mt < 4; mt++) {
                int r = wM * 64 + mt * 16 + g4;
                float4 af = make_float4(As[r][k + t4], As[r + 8][k + t4],
                                        As[r][k + t4 + 4], As[r + 8][k + t4 + 4]);
#pragma unroll
                for (int nt = 0; nt < 4; nt++)
                    mma_tf32(acc[mt][nt], af, bf[nt]);
            }
        }
        __syncthreads();
    }

#pragma unroll
    for (int mt = 0; mt < 4; mt++) {
        int r0 = mBase + wM * 64 + mt * 16 + g4;
        int r1 = r0 + 8;
#pragma unroll
        for (int nt = 0; nt < 4; nt++) {
            int n0 = nBase + wN * 32 + nt * 8 + t4 * 2;
            float2 bv = *(const float2*)(g_b0p + n0);
            *(float2*)(g_G0 + (size_t)r0 * G_ + n0) =
                make_float2(acc[mt][nt][0] + bv.x, acc[mt][nt][1] + bv.y);
            *(float2*)(g_G0 + (size_t)r1 * G_ + n0) =
                make_float2(acc[mt][nt][2] + bv.x, acc[mt][nt][3] + bv.y);
        }
    }
}

// ---------------- persistent recurrent kernel (R6 structure, fp16 h staging) ----
// Consumer warps 0..15: ks = w&7 (K-eighth), wm = w>>3 (prow half), full N=64.
// Producer warp 16 (tid 512): issues TMA for 16 K=128 chunks/step into 3 stages.
// Chunks 0..7: {B=h0(fp16), A0=Wh0, A1=Wx1}; chunks 8..15: {B=h1(fp16), A0slot=Wh1}.
// fp16 h halves staged bytes (896->640 KB/CTA/step) and B crossbar traffic.
// fp16->f32 values are exactly representable in tf32: no extra rounding at mma.

__global__ void __launch_bounds__(NTHR, 1) lstm_persist(float* __restrict__ out)
{
    extern __shared__ char sm[];
    float* sB = (float*)(sm + SM_BI);
    float* P  = (float*)sm;                       // partial buffer (overlay)
    const uint32_t smBase = (uint32_t)__cvta_generic_to_shared(sm);
    const uint32_t fullB  = smBase + SM_MB;
    const uint32_t emptyB = smBase + SM_MB + 24;

    const int c    = blockIdx.x;
    const int tid  = threadIdx.x;
    const int w    = tid >> 5;
    const int lane = tid & 31;
    const int ks   = w & 7;          // consumer K-eighth
    const int wm   = (w >> 3) & 1;   // prow half
    const int g4   = lane >> 2;
    const int t4   = lane & 3;
    const int v    = tid & 7;        // unit within CTA (consumers)
    const int b    = tid >> 3;       // batch (consumers, <64)
    const int u    = c * 8 + v;
    const int fidx = ((c * 256 + ((b >> 3) * 4 + (v & 3)) * 8 + (b & 7)) << 1) + (v >> 2);

    if (tid == 0) {
#pragma unroll
        for (int s = 0; s < NSTG; s++) {
            mbar_init(fullB  + s * 8, 1);
            mbar_init(emptyB + s * 8, 16);
        }
    }
    if (tid < 32) sB[tid] = g_b1p[c * 32 + tid];
    asm volatile("fence.proxy.async.shared::cta;" ::: "memory");
    __syncthreads();

    float c0r = 0.f, c1r = 0.f;

    // preamble: h0[0] from G0[0] (h=0), zero h1[-1] fragments
    if (tid < NCONS) {
        __half* h0w0 = g_h0I[0];
        __half* h1w0 = g_h1I[0];
        size_t gbase = (size_t)b * G_ + c * 32;
        float gi = g_G0[gbase + v];
        float go = g_G0[gbase + 16 + v];
        float gg = g_G0[gbase + 24 + v];
        float cn = sigmoidf_(gi) * tanhf(gg);
        float hn = sigmoidf_(go) * tanhf(cn);
        c0r = cn;
        h0w0[fidx] = __float2half(hn);
        h1w0[fidx] = __float2half(0.f);
    }
    gsync();

    const float4* a0B = g_A0 + (size_t)c * (NCH * 512);
    const float4* a1B = g_A1 + (size_t)c * (NCH * 512);
    const float4* a2B = g_A2 + (size_t)c * (NCH * 512);

    for (int t = 0; t < S_; t++) {
        const __half* bH0 = g_h0I[t & 1];          // h0[t]
        __half*       wH0 = g_h0I[(t + 1) & 1];
        const __half* bH1 = g_h1I[t & 1];          // h1[t-1]
        __half*       wH1 = g_h1I[(t + 1) & 1];

        // consumers: prefetch next layer0's G0 operands
        float p_gi = 0.f, p_gf = 0.f, p_go = 0.f, p_gg = 0.f;
        if (tid < NCONS && t + 1 < S_) {
            size_t gb = ((size_t)(t + 1) * B_ + b) * G_ + c * 32;
            p_gi = g_G0[gb + v];
            p_gf = g_G0[gb + 8 + v];
            p_go = g_G0[gb + 16 + v];
            p_gg = g_G0[gb + 24 + v];
        }

        float acc0[8][4], acc1[8][4];
#pragma unroll
        for (int bt = 0; bt < 8; bt++)
#pragma unroll
            for (int e = 0; e < 4; e++) { acc0[bt][e] = 0.f; acc1[bt][e] = 0.f; }

        if (tid == NCONS) {
            // ---------------- producer ----------------
            for (int ch = 0; ch < 16; ch++) {
                int s = ch % 3, n = ch / 3;
                if (t > 0 || ch >= 3) {
                    uint32_t par = (uint32_t)((((s != 0) ? (t & 1) : 0) + n + 1) & 1);
                    mbar_wait(emptyB + s * 8, par);
                }
                uint32_t sb = smBase + (uint32_t)s * STG_SZ;
                uint32_t fb = fullB + s * 8;
                if (ch < 8) {
                    mbar_expect_tx(fb, 49152u);
                    bulk_g2s(sb,          bH0 + (size_t)ch * 8192, 16384, fb);
                    bulk_g2s(sb + 16384,  a0B + (size_t)ch * 1024, 16384, fb);
                    bulk_g2s(sb + 32768,  a1B + (size_t)ch * 1024, 16384, fb);
                } else {
                    int cc = ch - 8;
                    mbar_expect_tx(fb, 32768u);
                    bulk_g2s(sb,          bH1 + (size_t)cc * 8192, 16384, fb);
                    bulk_g2s(sb + 16384,  a2B + (size_t)cc * 1024, 16384, fb);
                }
            }
        } else if (tid < NCONS) {
            // ---------------- consumers ----------------
            // chunks 0..7 : Wh0 -> acc0, Wx1 -> acc1  (B = h0[t], fp16 pairs)
            for (int ch = 0; ch < 8; ch++) {
                int s = ch % 3, n = ch / 3;
                uint32_t par = (uint32_t)((((s != 0) ? (t & 1) : 0) + n) & 1);
                mbar_wait(fullB + s * 8, par);
                const char* st = sm + s * STG_SZ;
                const float4* A0f = (const float4*)(st + 16384);
                const float4* A1f = (const float4*)(st + 32768);
#pragma unroll
                for (int half = 0; half < 2; half++) {
                    int aidx = half * 512 + (wm * 8 + ks) * 32 + lane;
                    float4 a0 = A0f[aidx];
                    float4 a1 = A1f[aidx];
                    const char* bb = st + (ks + half * 8) * 1024 + t4 * 32 + g4 * 4;
#pragma unroll
                    for (int bt = 0; bt < 8; bt++) {
                        __half2 hh = *(const __half2*)(bb + bt * 128);
                        float2 bf = __half22float2(hh);
                        mma_tf32(acc0[bt], a0, bf);
                        mma_tf32(acc1[bt], a1, bf);
                    }
                }
                if (lane == 0) mbar_arrive(emptyB + s * 8);
            }
            // chunks 8..15 : Wh1 -> acc1  (B = h1[t-1], fp16 pairs)
            for (int ch = 8; ch < 16; ch++) {
                int s = ch % 3, n = ch / 3;
                uint32_t par = (uint32_t)((((s != 0) ? (t & 1) : 0) + n) & 1);
                mbar_wait(fullB + s * 8, par);
                const char* st = sm + s * STG_SZ;
                const float4* A0f = (const float4*)(st + 16384);
#pragma unroll
                for (int half = 0; half < 2; half++) {
                    int aidx = half * 512 + (wm * 8 + ks) * 32 + lane;
                    float4 a0 = A0f[aidx];
                    const char* bb = st + (ks + half * 8) * 1024 + t4 * 32 + g4 * 4;
#pragma unroll
                    for (int bt = 0; bt < 8; bt++) {
                        __half2 hh = *(const __half2*)(bb + bt * 128);
                        float2 bf = __half22float2(hh);
                        mma_tf32(acc1[bt], a0, bf);
                    }
                }
                if (lane == 0) mbar_arrive(emptyB + s * 8);
            }
        }
        __syncthreads();   // all stages consumed; safe to overlay partials

        // ---- write K-split partials (row stride 68 floats, 4352 floats per ks) ----
        if (tid < NCONS) {
            int r0 = wm * 16 + g4;
            int base0 = ks * 4352;
#pragma unroll
            for (int bt = 0; bt < 8; bt++) {
                int col = bt * 8 + t4 * 2;
                *(float2*)&P[base0 + r0 * 68 + col]        = make_float2(acc0[bt][0], acc0[bt][1]);
                *(float2*)&P[base0 + (r0 + 8) * 68 + col]  = make_float2(acc0[bt][2], acc0[bt][3]);
                *(float2*)&P[base0 + 2176 + r0 * 68 + col]       = make_float2(acc1[bt][0], acc1[bt][1]);
                *(float2*)&P[base0 + 2176 + (r0 + 8) * 68 + col] = make_float2(acc1[bt][2], acc1[bt][3]);
            }
        }
        __syncthreads();

        // ---- reduce 8 partials + cell epilogues ----
        if (tid < NCONS) {
            float g0[4], g1[4];
#pragma unroll
            for (int q = 0; q < 4; q++) {
                int row = q * 8 + v;
                float s0 = 0.f, s1 = 0.f;
#pragma unroll
                for (int kr = 0; kr < 8; kr++) {
                    s0 += P[kr * 4352 + row * 68 + b];
                    s1 += P[kr * 4352 + 2176 + row * 68 + b];
                }
                g0[q] = s0; g1[q] = s1;
            }
            // layer 1 step t
            {
                float gi = g1[0] + sB[v];
                float gf = g1[1] + sB[8 + v];
                float go = g1[2] + sB[16 + v];
                float gg = g1[3] + sB[24 + v];
                float cn = sigmoidf_(gf) * c1r + sigmoidf_(gi) * tanhf(gg);
                float hn = sigmoidf_(go) * tanhf(cn);
                c1r = cn;
                out[((size_t)b * S_ + t) * H_ + u] = hn;
                wH1[fidx] = __float2half(hn);
                if (t == S_ - 1) {
                    out[(size_t)OUT_ELEMS + 1ull * BH_ + (size_t)b * H_ + u] = hn;
                    out[(size_t)OUT_ELEMS + 3ull * BH_ + (size_t)b * H_ + u] = cn;
                }
            }
            // layer 0 step t+1
            if (t < S_ - 1) {
                float gi = g0[0] + p_gi;
                float gf = g0[1] + p_gf;
                float go = g0[2] + p_go;
                float gg = g0[3] + p_gg;
                float cn = sigmoidf_(gf) * c0r + sigmoidf_(gi) * tanhf(gg);
                float hn = sigmoidf_(go) * tanhf(cn);
                c0r = cn;
                wH0[fidx] = __float2half(hn);
                if (t == S_ - 2) {
                    out[(size_t)OUT_ELEMS + (size_t)b * H_ + u]              = hn;
                    out[(size_t)OUT_ELEMS + 2ull * BH_ + (size_t)b * H_ + u] = cn;
                }
            }
        }
        if (t + 1 < S_) gsync();
    }
}

// ---------------- launch ----------------
extern "C" void kernel_launch(void* const* d_in, const int* in_sizes, int n_in,
                              void* d_out, int out_size)
{
    const float* x   = (const float*)d_in[0];
    const float* Wx0 = (const float*)d_in[1];
    const float* Wh0 = (const float*)d_in[2];
    const float* bx0 = (const float*)d_in[3];
    const float* bh0 = (const float*)d_in[4];
    const float* Wx1 = (const float*)d_in[5];
    const float* Wh1 = (const float*)d_in[6];
    const float* bx1 = (const float*)d_in[7];
    const float* bh1 = (const float*)d_in[8];
    float* out = (float*)d_out;

    static bool attr_done = false;
    if (!attr_done) {
        cudaFuncSetAttribute(lstm_persist,
                             cudaFuncAttributeMaxDynamicSharedMemorySize, SM_TOT);
        attr_done = true;
    }

    convert_nat<<<2048, 256>>>(Wx0, bx0, bh0, bx1, bh1);
    convert_frag<<<4096, 256>>>(Wh0, Wx1, Wh1);
    init_kernel<<<1, 32>>>();
    precompute_kernel<<<dim3(G_ / 128, (S_ * B_) / 128), 256>>>(x);
    lstm_persist<<<NCTA, NTHR, SM_TOT>>>(out);
}